// round 1
// baseline (speedup 1.0000x reference)
#include <cuda_runtime.h>
#include <math.h>

#define NB   64
#define NT   256
#define EMBD 512
#define RNN  1024
#define Z4   4096
#define HIDN 128
#define NLAB 4
#define KSPLIT 8

#define BM 64
#define BN 128
#define BK 16

// ---------------- scratch (static device memory; no allocations) ----------
__device__ float g_XW[(size_t)NT * NB * Z4];     // 256 MB: precomputed emb[x] @ W
__device__ float g_zpart[KSPLIT][NB * Z4];       // per-step k-split partials of h @ U
__device__ float g_h[NB * RNN];
__device__ float g_c[NB * RNN];
__device__ float g_pooled[NB * RNN];
__device__ int   g_active[NT];

// packed fp32x2 FMA (sm_103a: 2x the FFMA-3reg issue rate; ptxas never emits it)
__device__ __forceinline__ float2 ffma2(float2 a, float2 b, float2 c) {
    unsigned long long ra = reinterpret_cast<unsigned long long&>(a);
    unsigned long long rb = reinterpret_cast<unsigned long long&>(b);
    unsigned long long rc = reinterpret_cast<unsigned long long&>(c);
    unsigned long long rd;
    asm("fma.rn.f32x2 %0, %1, %2, %3;" : "=l"(rd) : "l"(ra), "l"(rb), "l"(rc));
    return reinterpret_cast<float2&>(rd);
}

// ---------------- prep: active-step flags --------------------------------
__global__ void prep_kernel(const int* __restrict__ x) {
    int t = threadIdx.x;
    if (t < NT) {
        int act = 0;
        for (int b = 0; b < NB; b++) act |= (x[b * NT + t] != 0);
        g_active[t] = act;
    }
}

__global__ void zero_kernel() {
    int i = blockIdx.x * blockDim.x + threadIdx.x;
    if (i < NB * RNN) { g_h[i] = 0.f; g_c[i] = 0.f; g_pooled[i] = 0.f; }
}

// ---------------- XW = emb[x] @ W  (one t per block-row, early-exit) -----
__global__ __launch_bounds__(128) void xw_kernel(const int* __restrict__ x,
                                                 const float* __restrict__ emb,
                                                 const float* __restrict__ W) {
    const int t = blockIdx.y;
    if (!g_active[t]) return;
    const int n0 = blockIdx.x * BN;

    __shared__ float As[2][BK][BM];
    __shared__ float Bs[2][BK][BN];
    __shared__ int idxs[NB];

    const int tid = threadIdx.x;
    if (tid < NB) idxs[tid] = x[tid * NT + t];
    __syncthreads();

    const int am   = tid >> 2;          // 0..31 (A row, second row = +32)
    const int ak   = (tid & 3) << 2;    // 0,4,8,12
    const int brow = tid >> 5;          // 0..3
    const int bcol = (tid & 31) << 2;   // 0..124

    const int tb = tid >> 4;            // 0..7
    const int tc = tid & 15;            // 0..15
    const int m0 = tb * 8;
    const int c0 = tc * 8;

    const size_t eA0 = (size_t)idxs[am] * EMBD;
    const size_t eA1 = (size_t)idxs[am + 32] * EMBD;

    float2 acc[8][4];
    #pragma unroll
    for (int i = 0; i < 8; i++)
        #pragma unroll
        for (int j = 0; j < 4; j++) acc[i][j] = make_float2(0.f, 0.f);

    float4 ra0, ra1, rb[4];

    // prologue: chunk 0 -> buf 0
    ra0 = *reinterpret_cast<const float4*>(emb + eA0 + ak);
    ra1 = *reinterpret_cast<const float4*>(emb + eA1 + ak);
    #pragma unroll
    for (int j = 0; j < 4; j++)
        rb[j] = *reinterpret_cast<const float4*>(W + (size_t)(brow + 4 * j) * Z4 + n0 + bcol);
    As[0][ak + 0][am] = ra0.x; As[0][ak + 1][am] = ra0.y;
    As[0][ak + 2][am] = ra0.z; As[0][ak + 3][am] = ra0.w;
    As[0][ak + 0][am + 32] = ra1.x; As[0][ak + 1][am + 32] = ra1.y;
    As[0][ak + 2][am + 32] = ra1.z; As[0][ak + 3][am + 32] = ra1.w;
    #pragma unroll
    for (int j = 0; j < 4; j++)
        *reinterpret_cast<float4*>(&Bs[0][brow + 4 * j][bcol]) = rb[j];
    __syncthreads();

    const int nch = EMBD / BK;  // 32
    for (int ch = 0; ch < nch; ch++) {
        const int buf = ch & 1;
        if (ch + 1 < nch) {
            const int k0 = (ch + 1) * BK;
            ra0 = *reinterpret_cast<const float4*>(emb + eA0 + k0 + ak);
            ra1 = *reinterpret_cast<const float4*>(emb + eA1 + k0 + ak);
            #pragma unroll
            for (int j = 0; j < 4; j++)
                rb[j] = *reinterpret_cast<const float4*>(W + (size_t)(k0 + brow + 4 * j) * Z4 + n0 + bcol);
        }
        #pragma unroll
        for (int kk = 0; kk < BK; kk++) {
            const float4 a0 = *reinterpret_cast<const float4*>(&As[buf][kk][m0]);
            const float4 a1 = *reinterpret_cast<const float4*>(&As[buf][kk][m0 + 4]);
            const float4 b0 = *reinterpret_cast<const float4*>(&Bs[buf][kk][c0]);
            const float4 b1 = *reinterpret_cast<const float4*>(&Bs[buf][kk][c0 + 4]);
            float2 bv[4];
            bv[0] = make_float2(b0.x, b0.y); bv[1] = make_float2(b0.z, b0.w);
            bv[2] = make_float2(b1.x, b1.y); bv[3] = make_float2(b1.z, b1.w);
            const float av[8] = {a0.x, a0.y, a0.z, a0.w, a1.x, a1.y, a1.z, a1.w};
            #pragma unroll
            for (int i = 0; i < 8; i++) {
                const float2 as = make_float2(av[i], av[i]);
                #pragma unroll
                for (int j = 0; j < 4; j++) acc[i][j] = ffma2(as, bv[j], acc[i][j]);
            }
        }
        if (ch + 1 < nch) {
            const int nb = (ch + 1) & 1;
            As[nb][ak + 0][am] = ra0.x; As[nb][ak + 1][am] = ra0.y;
            As[nb][ak + 2][am] = ra0.z; As[nb][ak + 3][am] = ra0.w;
            As[nb][ak + 0][am + 32] = ra1.x; As[nb][ak + 1][am + 32] = ra1.y;
            As[nb][ak + 2][am + 32] = ra1.z; As[nb][ak + 3][am + 32] = ra1.w;
            #pragma unroll
            for (int j = 0; j < 4; j++)
                *reinterpret_cast<float4*>(&Bs[nb][brow + 4 * j][bcol]) = rb[j];
        }
        __syncthreads();
    }

    float* C = g_XW + (size_t)t * NB * Z4;
    #pragma unroll
    for (int i = 0; i < 8; i++) {
        const int row = m0 + i;
        float4 v0 = make_float4(acc[i][0].x, acc[i][0].y, acc[i][1].x, acc[i][1].y);
        float4 v1 = make_float4(acc[i][2].x, acc[i][2].y, acc[i][3].x, acc[i][3].y);
        *reinterpret_cast<float4*>(C + (size_t)row * Z4 + n0 + c0) = v0;
        *reinterpret_cast<float4*>(C + (size_t)row * Z4 + n0 + c0 + 4) = v1;
    }
}

// ---------------- per-step z-partials: zpart[ks] = h @ U[kslice] ---------
__global__ __launch_bounds__(128) void z_kernel(const float* __restrict__ U, int t) {
    if (!g_active[t]) return;
    const int n0 = blockIdx.x * BN;
    const int ks = blockIdx.y;
    const int kbase = ks * (RNN / KSPLIT);  // slices of 128

    __shared__ float As[2][BK][BM];
    __shared__ float Bs[2][BK][BN];

    const int tid = threadIdx.x;
    const int am   = tid >> 2;
    const int ak   = (tid & 3) << 2;
    const int brow = tid >> 5;
    const int bcol = (tid & 31) << 2;
    const int tb = tid >> 4;
    const int tc = tid & 15;
    const int m0 = tb * 8;
    const int c0 = tc * 8;

    float2 acc[8][4];
    #pragma unroll
    for (int i = 0; i < 8; i++)
        #pragma unroll
        for (int j = 0; j < 4; j++) acc[i][j] = make_float2(0.f, 0.f);

    float4 ra0, ra1, rb[4];

    ra0 = *reinterpret_cast<const float4*>(g_h + (size_t)am * RNN + kbase + ak);
    ra1 = *reinterpret_cast<const float4*>(g_h + (size_t)(am + 32) * RNN + kbase + ak);
    #pragma unroll
    for (int j = 0; j < 4; j++)
        rb[j] = *reinterpret_cast<const float4*>(U + (size_t)(kbase + brow + 4 * j) * Z4 + n0 + bcol);
    As[0][ak + 0][am] = ra0.x; As[0][ak + 1][am] = ra0.y;
    As[0][ak + 2][am] = ra0.z; As[0][ak + 3][am] = ra0.w;
    As[0][ak + 0][am + 32] = ra1.x; As[0][ak + 1][am + 32] = ra1.y;
    As[0][ak + 2][am + 32] = ra1.z; As[0][ak + 3][am + 32] = ra1.w;
    #pragma unroll
    for (int j = 0; j < 4; j++)
        *reinterpret_cast<float4*>(&Bs[0][brow + 4 * j][bcol]) = rb[j];
    __syncthreads();

    const int nch = (RNN / KSPLIT) / BK;  // 8
    for (int ch = 0; ch < nch; ch++) {
        const int buf = ch & 1;
        if (ch + 1 < nch) {
            const int k0 = kbase + (ch + 1) * BK;
            ra0 = *reinterpret_cast<const float4*>(g_h + (size_t)am * RNN + k0 + ak);
            ra1 = *reinterpret_cast<const float4*>(g_h + (size_t)(am + 32) * RNN + k0 + ak);
            #pragma unroll
            for (int j = 0; j < 4; j++)
                rb[j] = *reinterpret_cast<const float4*>(U + (size_t)(k0 + brow + 4 * j) * Z4 + n0 + bcol);
        }
        #pragma unroll
        for (int kk = 0; kk < BK; kk++) {
            const float4 a0 = *reinterpret_cast<const float4*>(&As[buf][kk][m0]);
            const float4 a1 = *reinterpret_cast<const float4*>(&As[buf][kk][m0 + 4]);
            const float4 b0 = *reinterpret_cast<const float4*>(&Bs[buf][kk][c0]);
            const float4 b1 = *reinterpret_cast<const float4*>(&Bs[buf][kk][c0 + 4]);
            float2 bv[4];
            bv[0] = make_float2(b0.x, b0.y); bv[1] = make_float2(b0.z, b0.w);
            bv[2] = make_float2(b1.x, b1.y); bv[3] = make_float2(b1.z, b1.w);
            const float av[8] = {a0.x, a0.y, a0.z, a0.w, a1.x, a1.y, a1.z, a1.w};
            #pragma unroll
            for (int i = 0; i < 8; i++) {
                const float2 as = make_float2(av[i], av[i]);
                #pragma unroll
                for (int j = 0; j < 4; j++) acc[i][j] = ffma2(as, bv[j], acc[i][j]);
            }
        }
        if (ch + 1 < nch) {
            const int nb = (ch + 1) & 1;
            As[nb][ak + 0][am] = ra0.x; As[nb][ak + 1][am] = ra0.y;
            As[nb][ak + 2][am] = ra0.z; As[nb][ak + 3][am] = ra0.w;
            As[nb][ak + 0][am + 32] = ra1.x; As[nb][ak + 1][am + 32] = ra1.y;
            As[nb][ak + 2][am + 32] = ra1.z; As[nb][ak + 3][am + 32] = ra1.w;
            #pragma unroll
            for (int j = 0; j < 4; j++)
                *reinterpret_cast<float4*>(&Bs[nb][brow + 4 * j][bcol]) = rb[j];
        }
        __syncthreads();
    }

    float* C = g_zpart[ks];
    #pragma unroll
    for (int i = 0; i < 8; i++) {
        const int row = m0 + i;
        float4 v0 = make_float4(acc[i][0].x, acc[i][0].y, acc[i][1].x, acc[i][1].y);
        float4 v1 = make_float4(acc[i][2].x, acc[i][2].y, acc[i][3].x, acc[i][3].y);
        *reinterpret_cast<float4*>(C + (size_t)row * Z4 + n0 + c0) = v0;
        *reinterpret_cast<float4*>(C + (size_t)row * Z4 + n0 + c0 + 4) = v1;
    }
}

// ---------------- LSTM cell update (per step) -----------------------------
__global__ void cell_kernel(const int* __restrict__ x, const float* __restrict__ bias, int t) {
    if (!g_active[t]) return;
    const int idx = blockIdx.x * blockDim.x + threadIdx.x;  // 0..65535
    const int b = idx >> 10;
    const int hid = idx & 1023;

    const float* xw = g_XW + ((size_t)t * NB + b) * Z4;
    float zi = bias[hid]            + xw[hid];
    float zf = bias[RNN + hid]      + xw[RNN + hid];
    float zg = bias[2 * RNN + hid]  + xw[2 * RNN + hid];
    float zo = bias[3 * RNN + hid]  + xw[3 * RNN + hid];
    #pragma unroll
    for (int s = 0; s < KSPLIT; s++) {
        const float* zp = g_zpart[s] + (size_t)b * Z4;
        zi += zp[hid]; zf += zp[RNN + hid]; zg += zp[2 * RNN + hid]; zo += zp[3 * RNN + hid];
    }
    const float si = 1.f / (1.f + expf(-zi));
    const float sf = 1.f / (1.f + expf(-zf));
    const float so = 1.f / (1.f + expf(-zo));
    const float tg = tanhf(zg);
    const float c_old = g_c[idx];
    const float cn = sf * c_old + si * tg;
    const float hn = so * tanhf(cn);
    const int xv = x[b * NT + t];
    if (xv != 0) { g_h[idx] = hn; g_c[idx] = cn; }
    if (xv == 2) g_pooled[idx] += hn;
}

// ---------------- head: pooled -> relu MLP -> softmax ---------------------
__global__ __launch_bounds__(128) void head_kernel(const float* __restrict__ W1,
                                                   const float* __restrict__ b1,
                                                   const float* __restrict__ W2,
                                                   const float* __restrict__ b2,
                                                   const float* __restrict__ Wc,
                                                   const float* __restrict__ bc,
                                                   float* __restrict__ out) {
    const int b = blockIdx.x;
    const int tid = threadIdx.x;
    __shared__ float sp[RNN];
    __shared__ float h1s[HIDN];
    __shared__ float h2s[HIDN];
    __shared__ float lg[NLAB];

    for (int k = tid; k < RNN; k += 128) sp[k] = g_pooled[(size_t)b * RNN + k];
    __syncthreads();

    float a = b1[tid];
    for (int k = 0; k < RNN; k++) a += sp[k] * W1[(size_t)k * HIDN + tid];
    h1s[tid] = fmaxf(a, 0.f);
    __syncthreads();

    float a2 = b2[tid];
    for (int k = 0; k < HIDN; k++) a2 += h1s[k] * W2[(size_t)k * HIDN + tid];
    h2s[tid] = fmaxf(a2, 0.f);
    __syncthreads();

    if (tid < NLAB) {
        float l = bc[tid];
        for (int k = 0; k < HIDN; k++) l += h2s[k] * Wc[(size_t)k * NLAB + tid];
        lg[tid] = l;
    }
    __syncthreads();
    if (tid == 0) {
        const float mx = fmaxf(fmaxf(lg[0], lg[1]), fmaxf(lg[2], lg[3]));
        const float e0 = expf(lg[0] - mx), e1 = expf(lg[1] - mx);
        const float e2 = expf(lg[2] - mx), e3 = expf(lg[3] - mx);
        const float s = e0 + e1 + e2 + e3;
        out[b * 4 + 0] = e0 / s; out[b * 4 + 1] = e1 / s;
        out[b * 4 + 2] = e2 / s; out[b * 4 + 3] = e3 / s;
    }
}

// ---------------- launcher ------------------------------------------------
extern "C" void kernel_launch(void* const* d_in, const int* in_sizes, int n_in,
                              void* d_out, int out_size) {
    const int*   x    = (const int*)d_in[0];
    const float* emb  = (const float*)d_in[1];
    const float* W    = (const float*)d_in[2];
    const float* U    = (const float*)d_in[3];
    const float* bias = (const float*)d_in[4];
    const float* W1   = (const float*)d_in[5];
    const float* b1   = (const float*)d_in[6];
    const float* W2   = (const float*)d_in[7];
    const float* b2   = (const float*)d_in[8];
    const float* Wc   = (const float*)d_in[9];
    const float* bc   = (const float*)d_in[10];
    float* out = (float*)d_out;

    prep_kernel<<<1, 256>>>(x);
    zero_kernel<<<256, 256>>>();
    xw_kernel<<<dim3(Z4 / BN, NT), 128>>>(x, emb, W);
    for (int t = 0; t < NT; t++) {
        z_kernel<<<dim3(Z4 / BN, KSPLIT), 128>>>(U, t);
        cell_kernel<<<256, 256>>>(x, bias, t);
    }
    head_kernel<<<NB, 128>>>(W1, b1, W2, b2, Wc, bc, out);
}